// round 12
// baseline (speedup 1.0000x reference)
#include <cuda_runtime.h>
#include <cuda_bf16.h>
#include <cstdint>
#include <cstddef>

constexpr int H = 192;
constexpr int W = 320;
constexpr int HW = H * W;
constexpr int B_ = 2;
constexpr int OMCH = 216;

// ---- device scratch ----
__device__ __align__(16) __nv_bfloat16 g_in1h[(size_t)B_ * HW * 144];
__device__ __align__(16) __nv_bfloat16 g_in1l[(size_t)B_ * HW * 144];
__device__ __align__(16) __nv_bfloat16 g_x2h[(size_t)B_ * HW * 64];
__device__ __align__(16) __nv_bfloat16 g_x2l[(size_t)B_ * HW * 64];
__device__ __align__(16) __nv_bfloat16 g_x3h[(size_t)B_ * HW * 64];
__device__ __align__(16) __nv_bfloat16 g_x3l[(size_t)B_ * HW * 64];
__device__ float g_om[(size_t)B_ * OMCH * HW];
// sampled-A for dcn GEMM: K = 8 groups * 10 taps(9+pad) * 8 ch = 640
__device__ __align__(16) __nv_bfloat16 g_sh[(size_t)B_ * HW * 640];
__device__ __align__(16) __nv_bfloat16 g_sl[(size_t)B_ * HW * 640];

// prepacked weights: rows of 24 bf16 (16 data + 8 pad)
constexpr int W1ROWS = 9 * 9 * 64;
constexpr int W2ROWS = 9 * 4 * 64;
constexpr int W3ROWS = 9 * 4 * 224;
constexpr int W4ROWS = 40 * 64;          // dcn GEMM: [cb][n]
constexpr int WROWS = W1ROWS + W2ROWS + W3ROWS + W4ROWS;
constexpr size_t W1OFF = 0;
constexpr size_t W2OFF = (size_t)W1ROWS * 24;
constexpr size_t W3OFF = (size_t)(W1ROWS + W2ROWS) * 24;
constexpr size_t W4OFF = (size_t)(W1ROWS + W2ROWS + W3ROWS) * 24;
__device__ __align__(16) __nv_bfloat16 g_wbh[(size_t)WROWS * 24];
__device__ __align__(16) __nv_bfloat16 g_wbl[(size_t)WROWS * 24];

// ---- helpers ----
__device__ __forceinline__ uint32_t smem_u32(const void* p) {
    uint32_t a;
    asm("{ .reg .u64 t; cvta.to.shared.u64 t, %1; cvt.u32.u64 %0, t; }" : "=r"(a) : "l"(p));
    return a;
}
__device__ __forceinline__ void ldsm4(uint32_t r[4], uint32_t a) {
    asm volatile("ldmatrix.sync.aligned.m8n8.x4.shared.b16 {%0,%1,%2,%3}, [%4];"
        : "=r"(r[0]), "=r"(r[1]), "=r"(r[2]), "=r"(r[3]) : "r"(a));
}
__device__ __forceinline__ void ldsm2(uint32_t r[2], uint32_t a) {
    asm volatile("ldmatrix.sync.aligned.m8n8.x2.shared.b16 {%0,%1}, [%2];"
        : "=r"(r[0]), "=r"(r[1]) : "r"(a));
}
__device__ __forceinline__ void mma16816(float c[4], const uint32_t a[4], uint32_t b0, uint32_t b1) {
    asm volatile("mma.sync.aligned.m16n8k16.row.col.f32.bf16.bf16.f32 "
        "{%0,%1,%2,%3},{%4,%5,%6,%7},{%8,%9},{%0,%1,%2,%3};"
        : "+f"(c[0]), "+f"(c[1]), "+f"(c[2]), "+f"(c[3])
        : "r"(a[0]), "r"(a[1]), "r"(a[2]), "r"(a[3]), "r"(b0), "r"(b1));
}
__device__ __forceinline__ float lrelu(float x) { return x >= 0.f ? x : 0.1f * x; }
__device__ __forceinline__ void split_bf16(float v, __nv_bfloat16& h, __nv_bfloat16& l) {
    h = __float2bfloat16(v);
    l = __float2bfloat16(v - __bfloat162float(h));
}

// ---- input converter: NCHW f32 concat -> [b][p][144] bf16 hi/lo ----
__global__ __launch_bounds__(256) void convert_in1(
    const float* __restrict__ wp, const float* __restrict__ rf, const float* __restrict__ fl)
{
    __shared__ float s[64 * 145];
    const int nb = HW / 64;
    const int b = blockIdx.x / nb;
    const int p0 = (blockIdx.x % nb) * 64;
    for (int idx = threadIdx.x; idx < 64 * 144; idx += 256) {
        int px = idx & 63, ci = idx >> 6;
        float v = 0.f;
        if (ci < 64)       v = wp[(size_t)(b * 64 + ci) * HW + p0 + px];
        else if (ci < 128) v = rf[(size_t)(b * 64 + ci - 64) * HW + p0 + px];
        else if (ci < 130) v = fl[(size_t)(b * 2 + ci - 128) * HW + p0 + px];
        s[px * 145 + ci] = v;
    }
    __syncthreads();
    size_t base = ((size_t)b * HW + p0) * 144;
    for (int o = threadIdx.x; o < 64 * 144; o += 256) {
        int px = o / 144, ci = o - px * 144;
        __nv_bfloat16 hb, lb;
        split_bf16(s[px * 145 + ci], hb, lb);
        g_in1h[base + o] = hb;
        g_in1l[base + o] = lb;
    }
}

// ---- weight prepack ----
__global__ __launch_bounds__(256) void prepackW(
    const float* __restrict__ w1, const float* __restrict__ w2,
    const float* __restrict__ wom, const float* __restrict__ wdcn)
{
    for (int row = blockIdx.x * 256 + threadIdx.x; row < WROWS; row += gridDim.x * 256) {
        size_t o = (size_t)row * 24;
        if (row >= W1ROWS + W2ROWS + W3ROWS) {
            // dcn GEMM weights: row = cb*64 + n ; ci = cb*16+j = g*80 + tap*8 + c
            int r = row - (W1ROWS + W2ROWS + W3ROWS);
            int cb = r >> 6, n = r & 63;
            for (int j = 0; j < 16; ++j) {
                int ci = cb * 16 + j;
                int g = ci / 80, rem = ci - g * 80;
                int tap = rem >> 3, c = rem & 7;
                float v = 0.f;
                if (tap < 9) v = wdcn[(size_t)n * 576 + (g * 8 + c) * 9 + tap];
                __nv_bfloat16 hb, lb;
                split_bf16(v, hb, lb);
                g_wbh[o + j] = hb;
                g_wbl[o + j] = lb;
            }
            for (int j = 16; j < 24; ++j) { g_wbh[o + j] = __float2bfloat16(0.f); g_wbl[o + j] = __float2bfloat16(0.f); }
            continue;
        }
        int tap, cb, n, CIN, COUT;
        const float* w;
        if (row < W1ROWS) {
            int r = row; tap = r / (9 * 64); cb = (r / 64) % 9; n = r & 63;
            CIN = 130; COUT = 64; w = w1;
        } else if (row < W1ROWS + W2ROWS) {
            int r = row - W1ROWS; tap = r / (4 * 64); cb = (r / 64) % 4; n = r & 63;
            CIN = 64; COUT = 64; w = w2;
        } else {
            int r = row - W1ROWS - W2ROWS; tap = r / (4 * 224); cb = (r / 224) % 4; n = r % 224;
            CIN = 64; COUT = 216; w = wom;
        }
        for (int j = 0; j < 16; ++j) {
            int ci = cb * 16 + j;
            float v = 0.f;
            if (ci < CIN && n < COUT) v = w[((size_t)n * CIN + ci) * 9 + tap];
            __nv_bfloat16 hb, lb;
            split_bf16(v, hb, lb);
            g_wbh[o + j] = hb;
            g_wbl[o + j] = lb;
        }
        for (int j = 16; j < 24; ++j) { g_wbh[o + j] = __float2bfloat16(0.f); g_wbl[o + j] = __float2bfloat16(0.f); }
    }
}

// ---- tensor-core conv/GEMM via mma.sync (bf16 hi/lo, fp32 accum) ----
// TAPA..TAPB selects taps: (0,9) = 3x3 conv; (4,5) = 1x1 GEMM over interleaved input.
template<int CINB, int COUT, int NPAD, bool OUT_BF16, bool DO_LRELU, int TAPA, int TAPB>
__global__ __launch_bounds__(256)
void convMMA(const __nv_bfloat16* __restrict__ inh, const __nv_bfloat16* __restrict__ inl,
             const __nv_bfloat16* __restrict__ wbh, const __nv_bfloat16* __restrict__ wbl,
             const float* __restrict__ bias,
             __nv_bfloat16* __restrict__ outh, __nv_bfloat16* __restrict__ outl,
             float* __restrict__ outf)
{
    constexpr int WN = (NPAD == 64) ? 2 : 4;
    constexpr int MROWS = 8 / WN;
    constexpr int NFR = NPAD / (8 * WN);
    constexpr int CINP = CINB * 16;
    constexpr int AROWS = MROWS + 2;
    constexpr int ASZ = AROWS * 34 * 48;
    constexpr int BSZ = NPAD * 48;

    extern __shared__ __align__(16) unsigned char sm[];
    unsigned char* sAh = sm;
    unsigned char* sAl = sm + ASZ;
    unsigned char* sBh = sm + 2 * ASZ;
    unsigned char* sBl = sm + 2 * ASZ + BSZ;
    const uint32_t aAh = smem_u32(sAh), aAl = smem_u32(sAl);
    const uint32_t aBh = smem_u32(sBh), aBl = smem_u32(sBl);

    const int tid = threadIdx.x;
    const int lane = tid & 31, warp = tid >> 5;
    const int wm = warp / WN, wn = warp % WN;
    const int x0 = (blockIdx.x % 10) * 32;
    const int y0 = (blockIdx.x / 10) * MROWS;
    const int b = blockIdx.y;

    float acc[2][NFR][4];
#pragma unroll
    for (int i = 0; i < 2; ++i)
#pragma unroll
        for (int f = 0; f < NFR; ++f)
#pragma unroll
            for (int r = 0; r < 4; ++r) acc[i][f][r] = 0.f;

    const size_t inbase = (size_t)b * HW * CINP;

    for (int cb = 0; cb < CINB; ++cb) {
        for (int tap = TAPA; tap < TAPB; ++tap) {
            __syncthreads();
            if (tap == TAPA) {
                for (int it = tid; it < AROWS * 34 * 2; it += 256) {
                    int half = it & 1, pix = it >> 1;
                    int tr = pix / 34, tx = pix - tr * 34;
                    int gy = y0 - 1 + tr, gx = x0 - 1 + tx;
                    uint4 vh = {0, 0, 0, 0}, vl = {0, 0, 0, 0};
                    if ((unsigned)gy < (unsigned)H && (unsigned)gx < (unsigned)W) {
                        size_t o = inbase + (size_t)(gy * W + gx) * CINP + cb * 16 + half * 8;
                        vh = *reinterpret_cast<const uint4*>(inh + o);
                        vl = *reinterpret_cast<const uint4*>(inl + o);
                    }
                    int so = pix * 48 + half * 16;
                    *reinterpret_cast<uint4*>(sAh + so) = vh;
                    *reinterpret_cast<uint4*>(sAl + so) = vl;
                }
            }
            {
                size_t wo = (size_t)((tap - TAPA) * CINB + cb) * NPAD * 24;
                const uint4* gh = reinterpret_cast<const uint4*>(wbh + wo);
                const uint4* gl = reinterpret_cast<const uint4*>(wbl + wo);
                for (int it = tid; it < NPAD * 3; it += 256) {
                    reinterpret_cast<uint4*>(sBh)[it] = gh[it];
                    reinterpret_cast<uint4*>(sBl)[it] = gl[it];
                }
            }
            __syncthreads();

            const int dy = tap / 3, dx = tap % 3;
            uint32_t ah[2][4], al[2][4];
#pragma unroll
            for (int i = 0; i < 2; ++i) {
                int row = (wm + dy) * 34 + i * 16 + dx + (lane & 15);
                uint32_t ad = row * 48 + ((lane >> 4) << 4);
                ldsm4(ah[i], aAh + ad);
                ldsm4(al[i], aAl + ad);
            }
#pragma unroll
            for (int jj = 0; jj < NFR / 2; ++jj) {
                int n0 = wn * (NFR * 8) + jj * 16;
                uint32_t bd = (uint32_t)(n0 + (lane & 7) + ((lane >> 4) << 3)) * 48 + (((lane >> 3) & 1) << 4);
                uint32_t bh[4], bl[4];
                ldsm4(bh, aBh + bd);
                ldsm4(bl, aBl + bd);
#pragma unroll
                for (int h = 0; h < 2; ++h) {
                    int f = jj * 2 + h;
#pragma unroll
                    for (int i = 0; i < 2; ++i) {
                        mma16816(acc[i][f], ah[i], bh[2 * h], bh[2 * h + 1]);
                        mma16816(acc[i][f], al[i], bh[2 * h], bh[2 * h + 1]);
                        mma16816(acc[i][f], ah[i], bl[2 * h], bl[2 * h + 1]);
                    }
                }
            }
            if (NFR & 1) {
                constexpr int f = (NFR > 0) ? NFR - 1 : 0;
                int n0 = wn * (NFR * 8) + f * 8;
                uint32_t bd = (uint32_t)(n0 + (lane & 7)) * 48 + (((lane >> 3) & 1) << 4);
                uint32_t bh[2], bl[2];
                ldsm2(bh, aBh + bd);
                ldsm2(bl, aBl + bd);
#pragma unroll
                for (int i = 0; i < 2; ++i) {
                    mma16816(acc[i][f], ah[i], bh[0], bh[1]);
                    mma16816(acc[i][f], al[i], bh[0], bh[1]);
                    mma16816(acc[i][f], ah[i], bl[0], bl[1]);
                }
            }
        }
    }

    // epilogue
#pragma unroll
    for (int i = 0; i < 2; ++i) {
#pragma unroll
        for (int f = 0; f < NFR; ++f) {
            int n = wn * (NFR * 8) + f * 8 + (lane & 3) * 2;
            float b0 = 0.f, b1 = 0.f;
            if (n < COUT) { b0 = bias[n]; b1 = bias[n + 1]; }
#pragma unroll
            for (int h = 0; h < 2; ++h) {
                int rx = i * 16 + (lane >> 2) + h * 8;
                int y = y0 + wm, x = x0 + rx;
                size_t p = (size_t)y * W + x;
                float v0 = acc[i][f][2 * h] + b0;
                float v1 = acc[i][f][2 * h + 1] + b1;
                if (DO_LRELU) { v0 = lrelu(v0); v1 = lrelu(v1); }
                if (OUT_BF16) {
                    size_t o = ((size_t)b * HW + p) * 64 + n;
                    __nv_bfloat16 h0, l0, h1, l1;
                    split_bf16(v0, h0, l0);
                    split_bf16(v1, h1, l1);
                    *reinterpret_cast<__nv_bfloat162*>(outh + o) = __halves2bfloat162(h0, h1);
                    *reinterpret_cast<__nv_bfloat162*>(outl + o) = __halves2bfloat162(l0, l1);
                } else if (n < COUT) {
                    outf[((size_t)b * COUT + n) * HW + p] = v0;
                    outf[((size_t)b * COUT + n + 1) * HW + p] = v1;
                }
            }
        }
    }
}

// ---- dcn sampler: bilinear gather + mask, emits bf16 hi/lo A[p][640] ----
__global__ __launch_bounds__(256, 2)
void sampler_kernel(const float* __restrict__ xin, const float* __restrict__ flows,
                    const float* __restrict__ om,
                    __nv_bfloat16* __restrict__ sh, __nv_bfloat16* __restrict__ sl)
{
    extern __shared__ float s_x[];   // [49*49 pixels][8 ch] = 76832 B

    const int t = threadIdx.x;
    const int x0 = (blockIdx.x % 20) * 16, y0 = (blockIdx.x / 20) * 16;
    const int b = blockIdx.y;
    const int px = x0 + (t & 15), pyq = y0 + (t >> 4);
    const int ry0 = y0 - 16, rx0 = x0 - 16;
    const int p = pyq * W + px;

    const float fl_x = flows[(size_t)(b * 2 + 0) * HW + p];
    const float fl_y = flows[(size_t)(b * 2 + 1) * HW + p];
    const float* omp = om + (size_t)b * OMCH * HW + p;
    const float* xb  = xin + (size_t)b * 64 * HW;
    const size_t obase = ((size_t)b * HW + p) * 640;

    for (int g = 0; g < 8; ++g) {
        if (g) __syncthreads();
        // stage halo, channel-interleaved (c innermost -> conflict-free STS)
        for (int idx = t; idx < 49 * 49 * 8; idx += 256) {
            int c = idx & 7, pix = idx >> 3;
            int r = pix / 49, cc = pix - r * 49;
            int gy = ry0 + r, gx = rx0 + cc;
            float v = 0.f;
            if ((unsigned)gy < (unsigned)H && (unsigned)gx < (unsigned)W)
                v = xb[(size_t)(g * 8 + c) * HW + gy * W + gx];
            s_x[pix * 8 + c] = v;
        }
        __syncthreads();

#pragma unroll 3
        for (int k = 0; k < 9; ++k) {
            float offy = omp[(size_t)(g * 18 + 2 * k) * HW] + fl_y;
            float offx = omp[(size_t)(g * 18 + 2 * k + 1) * HW] + fl_x;
            float mraw = omp[(size_t)(144 + g * 9 + k) * HW];
            float m = 1.f / (1.f + __expf(-mraw));

            float pyf = (float)(pyq + (k / 3) - 1) + offy;
            float pxf = (float)(px + (k % 3) - 1) + offx;
            float fy = floorf(pyf), fx = floorf(pxf);
            int iy = (int)fy, ix = (int)fx;
            float wy = pyf - fy, wx = pxf - fx;

            float c11 = wy * wx * m;
            float c10 = wy * m - c11;
            float c01 = wx * m - c11;
            float c00 = m - wy * m - c01;

            bool ok = (iy >= ry0) && (iy <= ry0 + 47) && (ix >= rx0) && (ix <= rx0 + 47);

            float v00[8], v01[8], v10[8], v11[8];
            if (ok) {
                int base = ((iy - ry0) * 49 + (ix - rx0)) * 8;
                float4 a0 = *reinterpret_cast<const float4*>(s_x + base);
                float4 a1 = *reinterpret_cast<const float4*>(s_x + base + 4);
                float4 b0 = *reinterpret_cast<const float4*>(s_x + base + 8);
                float4 b1 = *reinterpret_cast<const float4*>(s_x + base + 12);
                float4 c0 = *reinterpret_cast<const float4*>(s_x + base + 392);
                float4 c1 = *reinterpret_cast<const float4*>(s_x + base + 396);
                float4 d0 = *reinterpret_cast<const float4*>(s_x + base + 400);
                float4 d1 = *reinterpret_cast<const float4*>(s_x + base + 404);
                v00[0]=a0.x; v00[1]=a0.y; v00[2]=a0.z; v00[3]=a0.w; v00[4]=a1.x; v00[5]=a1.y; v00[6]=a1.z; v00[7]=a1.w;
                v01[0]=b0.x; v01[1]=b0.y; v01[2]=b0.z; v01[3]=b0.w; v01[4]=b1.x; v01[5]=b1.y; v01[6]=b1.z; v01[7]=b1.w;
                v10[0]=c0.x; v10[1]=c0.y; v10[2]=c0.z; v10[3]=c0.w; v10[4]=c1.x; v10[5]=c1.y; v10[6]=c1.z; v10[7]=c1.w;
                v11[0]=d0.x; v11[1]=d0.y; v11[2]=d0.z; v11[3]=d0.w; v11[4]=d1.x; v11[5]=d1.y; v11[6]=d1.z; v11[7]=d1.w;
            } else {
                bool y0o = (unsigned)iy < (unsigned)H, y1o = (unsigned)(iy + 1) < (unsigned)H;
                bool x0o = (unsigned)ix < (unsigned)W, x1o = (unsigned)(ix + 1) < (unsigned)W;
#pragma unroll
                for (int c = 0; c < 8; ++c) {
                    const float* xp = xb + (size_t)(g * 8 + c) * HW;
                    v00[c] = (y0o && x0o) ? xp[iy * W + ix] : 0.f;
                    v01[c] = (y0o && x1o) ? xp[iy * W + ix + 1] : 0.f;
                    v10[c] = (y1o && x0o) ? xp[(iy + 1) * W + ix] : 0.f;
                    v11[c] = (y1o && x1o) ? xp[(iy + 1) * W + ix + 1] : 0.f;
                }
            }

            uint32_t hp[4], lp[4];
#pragma unroll
            for (int c2 = 0; c2 < 4; ++c2) {
                float u0 = fmaf(v00[2*c2],   c00, fmaf(v01[2*c2],   c01, fmaf(v10[2*c2],   c10, v11[2*c2]   * c11)));
                float u1 = fmaf(v00[2*c2+1], c00, fmaf(v01[2*c2+1], c01, fmaf(v10[2*c2+1], c10, v11[2*c2+1] * c11)));
                __nv_bfloat16 h0, l0, h1, l1;
                split_bf16(u0, h0, l0);
                split_bf16(u1, h1, l1);
                __nv_bfloat162 hh = __halves2bfloat162(h0, h1);
                __nv_bfloat162 ll = __halves2bfloat162(l0, l1);
                hp[c2] = *reinterpret_cast<uint32_t*>(&hh);
                lp[c2] = *reinterpret_cast<uint32_t*>(&ll);
            }
            size_t ob = obase + g * 80 + k * 8;
            *reinterpret_cast<uint4*>(sh + ob) = make_uint4(hp[0], hp[1], hp[2], hp[3]);
            *reinterpret_cast<uint4*>(sl + ob) = make_uint4(lp[0], lp[1], lp[2], lp[3]);
        }
    }
}

// ---- launch ----
extern "C" void kernel_launch(void* const* d_in, const int* in_sizes, int n_in,
                              void* d_out, int out_size)
{
    (void)in_sizes; (void)n_in; (void)out_size;
    const float* nbr    = (const float*)d_in[0];
    const float* warped = (const float*)d_in[1];
    const float* ref    = (const float*)d_in[2];
    const float* flows  = (const float*)d_in[3];
    const float* w1     = (const float*)d_in[4];
    const float* b1     = (const float*)d_in[5];
    const float* w2     = (const float*)d_in[6];
    const float* b2     = (const float*)d_in[7];
    const float* w_om   = (const float*)d_in[8];
    const float* b_om   = (const float*)d_in[9];
    const float* w_dcn  = (const float*)d_in[10];
    const float* b_dcn  = (const float*)d_in[11];
    float* out = (float*)d_out;

    __nv_bfloat16 *in1h, *in1l, *x2h, *x2l, *x3h, *x3l, *wbh, *wbl, *sh, *sl;
    float* pm;
    cudaGetSymbolAddress((void**)&in1h, g_in1h);
    cudaGetSymbolAddress((void**)&in1l, g_in1l);
    cudaGetSymbolAddress((void**)&x2h, g_x2h);
    cudaGetSymbolAddress((void**)&x2l, g_x2l);
    cudaGetSymbolAddress((void**)&x3h, g_x3h);
    cudaGetSymbolAddress((void**)&x3l, g_x3l);
    cudaGetSymbolAddress((void**)&wbh, g_wbh);
    cudaGetSymbolAddress((void**)&wbl, g_wbl);
    cudaGetSymbolAddress((void**)&sh, g_sh);
    cudaGetSymbolAddress((void**)&sl, g_sl);
    cudaGetSymbolAddress((void**)&pm, g_om);

    convert_in1<<<B_ * (HW / 64), 256>>>(warped, ref, flows);
    prepackW<<<72, 256>>>(w1, w2, w_om, w_dcn);

    constexpr int ASM12 = 2 * (6 * 34 * 48) + 2 * (64 * 48);    // 25728
    constexpr int ASM3  = 2 * (4 * 34 * 48) + 2 * (224 * 48);   // 34560
    cudaFuncSetAttribute((const void*)convMMA<9, 64, 64, true, true, 0, 9>,
                         cudaFuncAttributeMaxDynamicSharedMemorySize, ASM12);
    cudaFuncSetAttribute((const void*)convMMA<4, 64, 64, true, true, 0, 9>,
                         cudaFuncAttributeMaxDynamicSharedMemorySize, ASM12);
    cudaFuncSetAttribute((const void*)convMMA<4, 216, 224, false, false, 0, 9>,
                         cudaFuncAttributeMaxDynamicSharedMemorySize, ASM3);
    cudaFuncSetAttribute((const void*)convMMA<40, 64, 64, false, true, 4, 5>,
                         cudaFuncAttributeMaxDynamicSharedMemorySize, ASM12);

    // conv1: 144ch interleaved -> 64, lrelu, bf16 out
    convMMA<9, 64, 64, true, true, 0, 9><<<dim3(10 * (H / 4), B_), 256, ASM12>>>(
        in1h, in1l, wbh + W1OFF, wbl + W1OFF, b1, x2h, x2l, nullptr);
    // conv2: 64 -> 64, lrelu, bf16 out
    convMMA<4, 64, 64, true, true, 0, 9><<<dim3(10 * (H / 4), B_), 256, ASM12>>>(
        x2h, x2l, wbh + W2OFF, wbl + W2OFF, b2, x3h, x3l, nullptr);
    // om conv: 64 -> 216 (pad 224), fp32 NCHW out
    convMMA<4, 216, 224, false, false, 0, 9><<<dim3(10 * (H / 2), B_), 256, ASM3>>>(
        x3h, x3l, wbh + W3OFF, wbl + W3OFF, b_om, nullptr, nullptr, pm);

    // dcn sampling -> interleaved bf16 A[p][640]
    constexpr int SAMP_SMEM = 49 * 49 * 8 * 4;   // 76832
    cudaFuncSetAttribute(sampler_kernel, cudaFuncAttributeMaxDynamicSharedMemorySize, SAMP_SMEM);
    sampler_kernel<<<dim3(240, B_), 256, SAMP_SMEM>>>(nbr, flows, pm, sh, sl);

    // dcn GEMM: K=640, 1x1 (tap 4 only), fp32 NCHW out + bias + lrelu
    convMMA<40, 64, 64, false, true, 4, 5><<<dim3(10 * (H / 4), B_), 256, ASM12>>>(
        sh, sl, wbh + W4OFF, wbl + W4OFF, b_dcn, nullptr, nullptr, out);
}

// round 15
// speedup vs baseline: 1.0821x; 1.0821x over previous
#include <cuda_runtime.h>
#include <cuda_bf16.h>
#include <cstdint>
#include <cstddef>

constexpr int H = 192;
constexpr int W = 320;
constexpr int HW = H * W;
constexpr int B_ = 2;
constexpr int OMCH = 216;

// ---- device scratch ----
__device__ __align__(16) __nv_bfloat16 g_in1h[(size_t)B_ * HW * 144];
__device__ __align__(16) __nv_bfloat16 g_in1l[(size_t)B_ * HW * 144];
__device__ __align__(16) __nv_bfloat16 g_x2h[(size_t)B_ * HW * 64];
__device__ __align__(16) __nv_bfloat16 g_x2l[(size_t)B_ * HW * 64];
__device__ __align__(16) __nv_bfloat16 g_x3h[(size_t)B_ * HW * 64];
__device__ __align__(16) __nv_bfloat16 g_x3l[(size_t)B_ * HW * 64];
__device__ float g_om[(size_t)B_ * OMCH * HW];
// sampled-A for dcn GEMM: K = 8 groups * 10 taps(9+pad) * 8 ch = 640
__device__ __align__(16) __nv_bfloat16 g_sh[(size_t)B_ * HW * 640];
__device__ __align__(16) __nv_bfloat16 g_sl[(size_t)B_ * HW * 640];

// prepacked weights: rows of 24 bf16 (16 data + 8 pad)
constexpr int W1ROWS = 9 * 9 * 64;
constexpr int W2ROWS = 9 * 4 * 64;
constexpr int W3ROWS = 9 * 4 * 224;
constexpr int W4ROWS = 40 * 64;          // dcn GEMM: [cb][n]
constexpr int WROWS = W1ROWS + W2ROWS + W3ROWS + W4ROWS;
constexpr size_t W1OFF = 0;
constexpr size_t W2OFF = (size_t)W1ROWS * 24;
constexpr size_t W3OFF = (size_t)(W1ROWS + W2ROWS) * 24;
constexpr size_t W4OFF = (size_t)(W1ROWS + W2ROWS + W3ROWS) * 24;
__device__ __align__(16) __nv_bfloat16 g_wbh[(size_t)WROWS * 24];
__device__ __align__(16) __nv_bfloat16 g_wbl[(size_t)WROWS * 24];

// ---- helpers ----
__device__ __forceinline__ uint32_t smem_u32(const void* p) {
    uint32_t a;
    asm("{ .reg .u64 t; cvta.to.shared.u64 t, %1; cvt.u32.u64 %0, t; }" : "=r"(a) : "l"(p));
    return a;
}
__device__ __forceinline__ void ldsm4(uint32_t r[4], uint32_t a) {
    asm volatile("ldmatrix.sync.aligned.m8n8.x4.shared.b16 {%0,%1,%2,%3}, [%4];"
        : "=r"(r[0]), "=r"(r[1]), "=r"(r[2]), "=r"(r[3]) : "r"(a));
}
__device__ __forceinline__ void ldsm2(uint32_t r[2], uint32_t a) {
    asm volatile("ldmatrix.sync.aligned.m8n8.x2.shared.b16 {%0,%1}, [%2];"
        : "=r"(r[0]), "=r"(r[1]) : "r"(a));
}
__device__ __forceinline__ void mma16816(float c[4], const uint32_t a[4], uint32_t b0, uint32_t b1) {
    asm volatile("mma.sync.aligned.m16n8k16.row.col.f32.bf16.bf16.f32 "
        "{%0,%1,%2,%3},{%4,%5,%6,%7},{%8,%9},{%0,%1,%2,%3};"
        : "+f"(c[0]), "+f"(c[1]), "+f"(c[2]), "+f"(c[3])
        : "r"(a[0]), "r"(a[1]), "r"(a[2]), "r"(a[3]), "r"(b0), "r"(b1));
}
__device__ __forceinline__ float lrelu(float x) { return x >= 0.f ? x : 0.1f * x; }
__device__ __forceinline__ void split_bf16(float v, __nv_bfloat16& h, __nv_bfloat16& l) {
    h = __float2bfloat16(v);
    l = __float2bfloat16(v - __bfloat162float(h));
}

// ---- input converter: NCHW f32 concat -> [b][p][144] bf16 hi/lo ----
__global__ __launch_bounds__(256) void convert_in1(
    const float* __restrict__ wp, const float* __restrict__ rf, const float* __restrict__ fl)
{
    __shared__ float s[64 * 145];
    const int nb = HW / 64;
    const int b = blockIdx.x / nb;
    const int p0 = (blockIdx.x % nb) * 64;
    for (int idx = threadIdx.x; idx < 64 * 144; idx += 256) {
        int px = idx & 63, ci = idx >> 6;
        float v = 0.f;
        if (ci < 64)       v = wp[(size_t)(b * 64 + ci) * HW + p0 + px];
        else if (ci < 128) v = rf[(size_t)(b * 64 + ci - 64) * HW + p0 + px];
        else if (ci < 130) v = fl[(size_t)(b * 2 + ci - 128) * HW + p0 + px];
        s[px * 145 + ci] = v;
    }
    __syncthreads();
    size_t base = ((size_t)b * HW + p0) * 144;
    for (int o = threadIdx.x; o < 64 * 144; o += 256) {
        int px = o / 144, ci = o - px * 144;
        __nv_bfloat16 hb, lb;
        split_bf16(s[px * 145 + ci], hb, lb);
        g_in1h[base + o] = hb;
        g_in1l[base + o] = lb;
    }
}

// ---- weight prepack ----
__global__ __launch_bounds__(256) void prepackW(
    const float* __restrict__ w1, const float* __restrict__ w2,
    const float* __restrict__ wom, const float* __restrict__ wdcn)
{
    for (int row = blockIdx.x * 256 + threadIdx.x; row < WROWS; row += gridDim.x * 256) {
        size_t o = (size_t)row * 24;
        if (row >= W1ROWS + W2ROWS + W3ROWS) {
            int r = row - (W1ROWS + W2ROWS + W3ROWS);
            int cb = r >> 6, n = r & 63;
            for (int j = 0; j < 16; ++j) {
                int ci = cb * 16 + j;
                int g = ci / 80, rem = ci - g * 80;
                int tap = rem >> 3, c = rem & 7;
                float v = 0.f;
                if (tap < 9) v = wdcn[(size_t)n * 576 + (g * 8 + c) * 9 + tap];
                __nv_bfloat16 hb, lb;
                split_bf16(v, hb, lb);
                g_wbh[o + j] = hb;
                g_wbl[o + j] = lb;
            }
            for (int j = 16; j < 24; ++j) { g_wbh[o + j] = __float2bfloat16(0.f); g_wbl[o + j] = __float2bfloat16(0.f); }
            continue;
        }
        int tap, cb, n, CIN, COUT;
        const float* w;
        if (row < W1ROWS) {
            int r = row; tap = r / (9 * 64); cb = (r / 64) % 9; n = r & 63;
            CIN = 130; COUT = 64; w = w1;
        } else if (row < W1ROWS + W2ROWS) {
            int r = row - W1ROWS; tap = r / (4 * 64); cb = (r / 64) % 4; n = r & 63;
            CIN = 64; COUT = 64; w = w2;
        } else {
            int r = row - W1ROWS - W2ROWS; tap = r / (4 * 224); cb = (r / 224) % 4; n = r % 224;
            CIN = 64; COUT = 216; w = wom;
        }
        for (int j = 0; j < 16; ++j) {
            int ci = cb * 16 + j;
            float v = 0.f;
            if (ci < CIN && n < COUT) v = w[((size_t)n * CIN + ci) * 9 + tap];
            __nv_bfloat16 hb, lb;
            split_bf16(v, hb, lb);
            g_wbh[o + j] = hb;
            g_wbl[o + j] = lb;
        }
        for (int j = 16; j < 24; ++j) { g_wbh[o + j] = __float2bfloat16(0.f); g_wbl[o + j] = __float2bfloat16(0.f); }
    }
}

// ---- tensor-core conv/GEMM via mma.sync (bf16 hi/lo, fp32 accum) ----
// TAPA..TAPB selects taps; TAPGRP taps share one B-staging sync window.
// Weight arrays are indexed with TAPA-relative tap indices.
template<int CINB, int COUT, int NPAD, bool OUT_BF16, bool DO_LRELU, int TAPA, int TAPB, int TAPGRP>
__global__ __launch_bounds__(256)
void convMMA(const __nv_bfloat16* __restrict__ inh, const __nv_bfloat16* __restrict__ inl,
             const __nv_bfloat16* __restrict__ wbh, const __nv_bfloat16* __restrict__ wbl,
             const float* __restrict__ bias,
             __nv_bfloat16* __restrict__ outh, __nv_bfloat16* __restrict__ outl,
             float* __restrict__ outf)
{
    constexpr int TAPN = TAPB - TAPA;
    static_assert(TAPN % TAPGRP == 0, "tap group");
    constexpr int WN = (NPAD == 64) ? 2 : 4;
    constexpr int MROWS = 8 / WN;
    constexpr int NFR = NPAD / (8 * WN);
    constexpr int CINP = CINB * 16;
    constexpr int AROWS = MROWS + 2;
    constexpr int ASZ = AROWS * 34 * 48;
    constexpr int BSZ = TAPGRP * NPAD * 48;

    extern __shared__ __align__(16) unsigned char sm[];
    unsigned char* sAh = sm;
    unsigned char* sAl = sm + ASZ;
    unsigned char* sBh = sm + 2 * ASZ;
    unsigned char* sBl = sm + 2 * ASZ + BSZ;
    const uint32_t aAh = smem_u32(sAh), aAl = smem_u32(sAl);
    const uint32_t aBh = smem_u32(sBh), aBl = smem_u32(sBl);

    const int tid = threadIdx.x;
    const int lane = tid & 31, warp = tid >> 5;
    const int wm = warp / WN, wn = warp % WN;
    const int x0 = (blockIdx.x % 10) * 32;
    const int y0 = (blockIdx.x / 10) * MROWS;
    const int b = blockIdx.y;

    float acc[2][NFR][4];
#pragma unroll
    for (int i = 0; i < 2; ++i)
#pragma unroll
        for (int f = 0; f < NFR; ++f)
#pragma unroll
            for (int r = 0; r < 4; ++r) acc[i][f][r] = 0.f;

    const size_t inbase = (size_t)b * HW * CINP;

    for (int cb = 0; cb < CINB; ++cb) {
        for (int tg = 0; tg < TAPN; tg += TAPGRP) {
            __syncthreads();
            if (tg == 0) {
                for (int it = tid; it < AROWS * 34 * 2; it += 256) {
                    int half = it & 1, pix = it >> 1;
                    int tr = pix / 34, tx = pix - tr * 34;
                    int gy = y0 - 1 + tr, gx = x0 - 1 + tx;
                    uint4 vh = {0, 0, 0, 0}, vl = {0, 0, 0, 0};
                    if ((unsigned)gy < (unsigned)H && (unsigned)gx < (unsigned)W) {
                        size_t o = inbase + (size_t)(gy * W + gx) * CINP + cb * 16 + half * 8;
                        vh = *reinterpret_cast<const uint4*>(inh + o);
                        vl = *reinterpret_cast<const uint4*>(inl + o);
                    }
                    int so = pix * 48 + half * 16;
                    *reinterpret_cast<uint4*>(sAh + so) = vh;
                    *reinterpret_cast<uint4*>(sAl + so) = vl;
                }
            }
            // stage B for TAPGRP taps (pre-packed rows; TAPA-relative tap index)
            for (int it = tid; it < TAPGRP * NPAD * 3; it += 256) {
                int tt = it / (NPAD * 3);
                int r  = it - tt * (NPAD * 3);
                size_t wo = (size_t)((tg + tt) * CINB + cb) * (NPAD * 3);
                reinterpret_cast<uint4*>(sBh)[it] = reinterpret_cast<const uint4*>(wbh)[wo + r];
                reinterpret_cast<uint4*>(sBl)[it] = reinterpret_cast<const uint4*>(wbl)[wo + r];
            }
            __syncthreads();

#pragma unroll
            for (int t2 = 0; t2 < TAPGRP; ++t2) {
                const int tap = TAPA + tg + t2;
                const int dy = tap / 3, dx = tap % 3;
                const uint32_t bO = (uint32_t)t2 * (NPAD * 48);
                uint32_t ah[2][4], al[2][4];
#pragma unroll
                for (int i = 0; i < 2; ++i) {
                    int row = (wm + dy) * 34 + i * 16 + dx + (lane & 15);
                    uint32_t ad = row * 48 + ((lane >> 4) << 4);
                    ldsm4(ah[i], aAh + ad);
                    ldsm4(al[i], aAl + ad);
                }
#pragma unroll
                for (int jj = 0; jj < NFR / 2; ++jj) {
                    int n0 = wn * (NFR * 8) + jj * 16;
                    uint32_t bd = (uint32_t)(n0 + (lane & 7) + ((lane >> 4) << 3)) * 48 + (((lane >> 3) & 1) << 4);
                    uint32_t bh[4], bl[4];
                    ldsm4(bh, aBh + bO + bd);
                    ldsm4(bl, aBl + bO + bd);
#pragma unroll
                    for (int h = 0; h < 2; ++h) {
                        int f = jj * 2 + h;
#pragma unroll
                        for (int i = 0; i < 2; ++i) {
                            mma16816(acc[i][f], ah[i], bh[2 * h], bh[2 * h + 1]);
                            mma16816(acc[i][f], al[i], bh[2 * h], bh[2 * h + 1]);
                            mma16816(acc[i][f], ah[i], bl[2 * h], bl[2 * h + 1]);
                        }
                    }
                }
                if (NFR & 1) {
                    constexpr int f = (NFR > 0) ? NFR - 1 : 0;
                    int n0 = wn * (NFR * 8) + f * 8;
                    uint32_t bd = (uint32_t)(n0 + (lane & 7)) * 48 + (((lane >> 3) & 1) << 4);
                    uint32_t bh[2], bl[2];
                    ldsm2(bh, aBh + bO + bd);
                    ldsm2(bl, aBl + bO + bd);
#pragma unroll
                    for (int i = 0; i < 2; ++i) {
                        mma16816(acc[i][f], ah[i], bh[0], bh[1]);
                        mma16816(acc[i][f], al[i], bh[0], bh[1]);
                        mma16816(acc[i][f], ah[i], bl[0], bl[1]);
                    }
                }
            }
        }
    }

    // epilogue
#pragma unroll
    for (int i = 0; i < 2; ++i) {
#pragma unroll
        for (int f = 0; f < NFR; ++f) {
            int n = wn * (NFR * 8) + f * 8 + (lane & 3) * 2;
            float b0 = 0.f, b1 = 0.f;
            if (n < COUT) { b0 = bias[n]; b1 = bias[n + 1]; }
#pragma unroll
            for (int h = 0; h < 2; ++h) {
                int rx = i * 16 + (lane >> 2) + h * 8;
                int y = y0 + wm, x = x0 + rx;
                size_t p = (size_t)y * W + x;
                float v0 = acc[i][f][2 * h] + b0;
                float v1 = acc[i][f][2 * h + 1] + b1;
                if (DO_LRELU) { v0 = lrelu(v0); v1 = lrelu(v1); }
                if (OUT_BF16) {
                    size_t o = ((size_t)b * HW + p) * 64 + n;
                    __nv_bfloat16 h0, l0, h1, l1;
                    split_bf16(v0, h0, l0);
                    split_bf16(v1, h1, l1);
                    *reinterpret_cast<__nv_bfloat162*>(outh + o) = __halves2bfloat162(h0, h1);
                    *reinterpret_cast<__nv_bfloat162*>(outl + o) = __halves2bfloat162(l0, l1);
                } else if (n < COUT) {
                    outf[((size_t)b * COUT + n) * HW + p] = v0;
                    outf[((size_t)b * COUT + n + 1) * HW + p] = v1;
                }
            }
        }
    }
}

// ---- dcn sampler: bilinear gather + mask, emits bf16 hi/lo A[p][640] ----
// 16x16 pixel tile, halo 8 (region 32x32); out-of-halo -> global fallback.
__global__ __launch_bounds__(256, 3)
void sampler_kernel(const float* __restrict__ xin, const float* __restrict__ flows,
                    const float* __restrict__ om,
                    __nv_bfloat16* __restrict__ sh, __nv_bfloat16* __restrict__ sl)
{
    __shared__ float s_x[32 * 32 * 8];   // [pix][8ch] = 32 KB

    const int t = threadIdx.x;
    const int x0 = (blockIdx.x % 20) * 16, y0 = (blockIdx.x / 20) * 16;
    const int b = blockIdx.y;
    const int px = x0 + (t & 15), pyq = y0 + (t >> 4);
    const int ry0 = y0 - 8, rx0 = x0 - 8;
    const int p = pyq * W + px;

    const float fl_x = flows[(size_t)(b * 2 + 0) * HW + p];
    const float fl_y = flows[(size_t)(b * 2 + 1) * HW + p];
    const float* omp = om + (size_t)b * OMCH * HW + p;
    const float* xb  = xin + (size_t)b * 64 * HW;
    const size_t obase = ((size_t)b * HW + p) * 640;

    for (int g = 0; g < 8; ++g) {
        if (g) __syncthreads();
        // stage 32x32 halo region, channel-interleaved
        for (int idx = t; idx < 32 * 32 * 8; idx += 256) {
            int c = idx & 7, pix = idx >> 3;
            int r = pix >> 5, cc = pix & 31;
            int gy = ry0 + r, gx = rx0 + cc;
            float v = 0.f;
            if ((unsigned)gy < (unsigned)H && (unsigned)gx < (unsigned)W)
                v = xb[(size_t)(g * 8 + c) * HW + gy * W + gx];
            s_x[pix * 8 + c] = v;
        }
        __syncthreads();

#pragma unroll 3
        for (int k = 0; k < 9; ++k) {
            float offy = omp[(size_t)(g * 18 + 2 * k) * HW] + fl_y;
            float offx = omp[(size_t)(g * 18 + 2 * k + 1) * HW] + fl_x;
            float mraw = omp[(size_t)(144 + g * 9 + k) * HW];
            float m = 1.f / (1.f + __expf(-mraw));

            float pyf = (float)(pyq + (k / 3) - 1) + offy;
            float pxf = (float)(px + (k % 3) - 1) + offx;
            float fy = floorf(pyf), fx = floorf(pxf);
            int iy = (int)fy, ix = (int)fx;
            float wy = pyf - fy, wx = pxf - fx;

            float c11 = wy * wx * m;
            float c10 = wy * m - c11;
            float c01 = wx * m - c11;
            float c00 = m - wy * m - c01;

            bool ok = (iy >= ry0) && (iy <= ry0 + 30) && (ix >= rx0) && (ix <= rx0 + 30);

            float v00[8], v01[8], v10[8], v11[8];
            if (ok) {
                int base = (((iy - ry0) << 5) + (ix - rx0)) * 8;
                float4 a0 = *reinterpret_cast<const float4*>(s_x + base);
                float4 a1 = *reinterpret_cast<const float4*>(s_x + base + 4);
                float4 b0 = *reinterpret_cast<const float4*>(s_x + base + 8);
                float4 b1 = *reinterpret_cast<const float4*>(s_x + base + 12);
                float4 c0 = *reinterpret_cast<const float4*>(s_x + base + 256);
                float4 c1 = *reinterpret_cast<const float4*>(s_x + base + 260);
                float4 d0 = *reinterpret_cast<const float4*>(s_x + base + 264);
                float4 d1 = *reinterpret_cast<const float4*>(s_x + base + 268);
                v00[0]=a0.x; v00[1]=a0.y; v00[2]=a0.z; v00[3]=a0.w; v00[4]=a1.x; v00[5]=a1.y; v00[6]=a1.z; v00[7]=a1.w;
                v01[0]=b0.x; v01[1]=b0.y; v01[2]=b0.z; v01[3]=b0.w; v01[4]=b1.x; v01[5]=b1.y; v01[6]=b1.z; v01[7]=b1.w;
                v10[0]=c0.x; v10[1]=c0.y; v10[2]=c0.z; v10[3]=c0.w; v10[4]=c1.x; v10[5]=c1.y; v10[6]=c1.z; v10[7]=c1.w;
                v11[0]=d0.x; v11[1]=d0.y; v11[2]=d0.z; v11[3]=d0.w; v11[4]=d1.x; v11[5]=d1.y; v11[6]=d1.z; v11[7]=d1.w;
            } else {
                bool y0o = (unsigned)iy < (unsigned)H, y1o = (unsigned)(iy + 1) < (unsigned)H;
                bool x0o = (unsigned)ix < (unsigned)W, x1o = (unsigned)(ix + 1) < (unsigned)W;
#pragma unroll
                for (int c = 0; c < 8; ++c) {
                    const float* xp = xb + (size_t)(g * 8 + c) * HW;
                    v00[c] = (y0o && x0o) ? xp[iy * W + ix] : 0.f;
                    v01[c] = (y0o && x1o) ? xp[iy * W + ix + 1] : 0.f;
                    v10[c] = (y1o && x0o) ? xp[(iy + 1) * W + ix] : 0.f;
                    v11[c] = (y1o && x1o) ? xp[(iy + 1) * W + ix + 1] : 0.f;
                }
            }

            uint32_t hp[4], lp[4];
#pragma unroll
            for (int c2 = 0; c2 < 4; ++c2) {
                float u0 = fmaf(v00[2*c2],   c00, fmaf(v01[2*c2],   c01, fmaf(v10[2*c2],   c10, v11[2*c2]   * c11)));
                float u1 = fmaf(v00[2*c2+1], c00, fmaf(v01[2*c2+1], c01, fmaf(v10[2*c2+1], c10, v11[2*c2+1] * c11)));
                __nv_bfloat16 h0, l0, h1, l1;
                split_bf16(u0, h0, l0);
                split_bf16(u1, h1, l1);
                __nv_bfloat162 hh = __halves2bfloat162(h0, h1);
                __nv_bfloat162 ll = __halves2bfloat162(l0, l1);
                hp[c2] = *reinterpret_cast<uint32_t*>(&hh);
                lp[c2] = *reinterpret_cast<uint32_t*>(&ll);
            }
            size_t ob = obase + g * 80 + k * 8;
            *reinterpret_cast<uint4*>(sh + ob) = make_uint4(hp[0], hp[1], hp[2], hp[3]);
            *reinterpret_cast<uint4*>(sl + ob) = make_uint4(lp[0], lp[1], lp[2], lp[3]);
        }
    }
}

// ---- launch ----
extern "C" void kernel_launch(void* const* d_in, const int* in_sizes, int n_in,
                              void* d_out, int out_size)
{
    (void)in_sizes; (void)n_in; (void)out_size;
    const float* nbr    = (const float*)d_in[0];
    const float* warped = (const float*)d_in[1];
    const float* ref    = (const float*)d_in[2];
    const float* flows  = (const float*)d_in[3];
    const float* w1     = (const float*)d_in[4];
    const float* b1     = (const float*)d_in[5];
    const float* w2     = (const float*)d_in[6];
    const float* b2     = (const float*)d_in[7];
    const float* w_om   = (const float*)d_in[8];
    const float* b_om   = (const float*)d_in[9];
    const float* w_dcn  = (const float*)d_in[10];
    const float* b_dcn  = (const float*)d_in[11];
    float* out = (float*)d_out;

    __nv_bfloat16 *in1h, *in1l, *x2h, *x2l, *x3h, *x3l, *wbh, *wbl, *sh, *sl;
    float* pm;
    cudaGetSymbolAddress((void**)&in1h, g_in1h);
    cudaGetSymbolAddress((void**)&in1l, g_in1l);
    cudaGetSymbolAddress((void**)&x2h, g_x2h);
    cudaGetSymbolAddress((void**)&x2l, g_x2l);
    cudaGetSymbolAddress((void**)&x3h, g_x3h);
    cudaGetSymbolAddress((void**)&x3l, g_x3l);
    cudaGetSymbolAddress((void**)&wbh, g_wbh);
    cudaGetSymbolAddress((void**)&wbl, g_wbl);
    cudaGetSymbolAddress((void**)&sh, g_sh);
    cudaGetSymbolAddress((void**)&sl, g_sl);
    cudaGetSymbolAddress((void**)&pm, g_om);

    convert_in1<<<B_ * (HW / 64), 256>>>(warped, ref, flows);
    prepackW<<<72, 256>>>(w1, w2, w_om, w_dcn);

    // smem: 2*ASZ + 2*TAPGRP*NPAD*48
    constexpr int SM_C12 = 2 * (6 * 34 * 48) + 2 * (9 * 64 * 48);   // 74880
    constexpr int SM_OM  = 2 * (4 * 34 * 48) + 2 * (3 * 224 * 48);  // 77568
    constexpr int SM_DG  = 2 * (6 * 34 * 48) + 2 * (1 * 64 * 48);   // 25728
    cudaFuncSetAttribute((const void*)convMMA<9, 64, 64, true, true, 0, 9, 9>,
                         cudaFuncAttributeMaxDynamicSharedMemorySize, SM_C12);
    cudaFuncSetAttribute((const void*)convMMA<4, 64, 64, true, true, 0, 9, 9>,
                         cudaFuncAttributeMaxDynamicSharedMemorySize, SM_C12);
    cudaFuncSetAttribute((const void*)convMMA<4, 216, 224, false, false, 0, 9, 3>,
                         cudaFuncAttributeMaxDynamicSharedMemorySize, SM_OM);
    cudaFuncSetAttribute((const void*)convMMA<40, 64, 64, false, true, 4, 5, 1>,
                         cudaFuncAttributeMaxDynamicSharedMemorySize, SM_DG);

    // conv1: 144ch interleaved -> 64, lrelu, bf16 out
    convMMA<9, 64, 64, true, true, 0, 9, 9><<<dim3(10 * (H / 4), B_), 256, SM_C12>>>(
        in1h, in1l, wbh + W1OFF, wbl + W1OFF, b1, x2h, x2l, nullptr);
    // conv2: 64 -> 64, lrelu, bf16 out
    convMMA<4, 64, 64, true, true, 0, 9, 9><<<dim3(10 * (H / 4), B_), 256, SM_C12>>>(
        x2h, x2l, wbh + W2OFF, wbl + W2OFF, b2, x3h, x3l, nullptr);
    // om conv: 64 -> 216 (pad 224), fp32 NCHW out
    convMMA<4, 216, 224, false, false, 0, 9, 3><<<dim3(10 * (H / 2), B_), 256, SM_OM>>>(
        x3h, x3l, wbh + W3OFF, wbl + W3OFF, b_om, nullptr, nullptr, pm);

    // dcn sampling -> interleaved bf16 A[p][640]
    sampler_kernel<<<dim3(240, B_), 256>>>(nbr, flows, pm, sh, sl);

    // dcn GEMM: K=640, 1x1 (tap 4 center), fp32 NCHW out + bias + lrelu
    convMMA<40, 64, 64, false, true, 4, 5, 1><<<dim3(10 * (H / 4), B_), 256, SM_DG>>>(
        sh, sl, wbh + W4OFF, wbl + W4OFF, b_dcn, nullptr, nullptr, out);
}